// round 9
// baseline (speedup 1.0000x reference)
#include <cuda_runtime.h>
#include <cstdint>

// ===========================================================================
// RSNN forward — fused producer/consumer overlap.
//  - 128 consumer CTAs (bids 0..127): persistent recurrent scan, 2 batches
//    per CTA, 512 threads (thread owns h=tid and h=tid+512). Guaranteed
//    resident in wave 1 -> no deadlock. Spin on per-M-tile flags.
//  - 4000 producer CTAs (bids 128..4127): fp32 SIMT GEMM inp = x @ w_in^T,
//    bitwise-identical FFMA order to the R1/R8 kernels that passed.
//  GEMM is FFMA-bound, scan is L2-bound -> they overlap almost freely.
// ===========================================================================

#define T_STEPS 250
#define BATCH   256
#define IN_F    700
#define HID     1024
#define OUT_F   20
#define M_TOTAL (T_STEPS * BATCH)   // 64000

#define ALPHA_S 0.9048374180359595f
#define ALPHA_N 0.9753099120283326f

#define BM 128
#define BN 128
#define BK 16
#define NTILE 44                    // ceil(700/16)
#define NGX (HID / BN)              // 8
#define NGY (M_TOTAL / BM)          // 500
#define NR  128                     // rsnn CTAs (2 batches each)

// ---- scratch (device globals) ----
__device__ float    g_inp[(size_t)M_TOTAL * HID];   // 262 MB
__device__ float    g_wrecT[(size_t)HID * HID];     // 4 MB
__device__ unsigned g_done[NGY];                    // per-M-tile completion count

// ---------------------------------------------------------------------------
__global__ void transpose_wrec(const float* __restrict__ w) {
    __shared__ float tile[32][33];
    int x0 = blockIdx.x * 32, y0 = blockIdx.y * 32;
    int tx = threadIdx.x, ty = threadIdx.y;
#pragma unroll
    for (int i = 0; i < 32; i += 8)
        tile[ty + i][tx] = w[(size_t)(y0 + ty + i) * HID + (x0 + tx)];
    __syncthreads();
#pragma unroll
    for (int i = 0; i < 32; i += 8)
        g_wrecT[(size_t)(x0 + ty + i) * HID + (y0 + tx)] = tile[tx][ty + i];
}

__global__ void zero_flags() {
    int i = blockIdx.x * blockDim.x + threadIdx.x;
    if (i < NGY) g_done[i] = 0u;
}

// ---------------------------------------------------------------------------
// shared-memory union: gemm tiles vs rsnn scan state
// ---------------------------------------------------------------------------
union SmemU {
    struct {
        float As[2][BK][BM];
        float Bs[2][BK][BN];
    } g;                                  // 32 KB
    struct {
        int   list[2][2][HID];            // [batch][parity][idx]
        int   cnt[2][2];
        int   c32[32];
        int   off[32];
        float out[2][OUT_F];
    } r;                                  // ~16.7 KB
};

// ---------------------------------------------------------------------------
__device__ __forceinline__ unsigned ld_acq(const unsigned* p) {
    unsigned v;
    asm volatile("ld.acquire.gpu.global.u32 %0, [%1];" : "=r"(v) : "l"(p));
    return v;
}

// ---------------------------------------------------------------------------
// producer: fp32 GEMM tile (R8 arithmetic, 512 threads)
// ---------------------------------------------------------------------------
__device__ void gemm_part(SmemU* sm, const float* __restrict__ X,
                          const float* __restrict__ W, int gbid) {
    int nx = gbid & (NGX - 1);
    int my = gbid >> 3;
    size_t bm = (size_t)my * BM;
    size_t bn = (size_t)nx * BN;

    int tid = threadIdx.x;
    int lrow = tid >> 2;            // 0..127
    int lk = (tid & 3) * 4;         // 0,4,8,12

    int ty = tid >> 4;              // 0..31 -> 4 rows
    int tx = tid & 15;              // 0..15 -> 8 cols

    float (*As)[BK][BM] = sm->g.As;
    float (*Bs)[BK][BN] = sm->g.Bs;

    const float* Arow = X + (bm + lrow) * IN_F;
    const float* Brow = W + (bn + lrow) * IN_F;

    float acc[4][8];
#pragma unroll
    for (int i = 0; i < 4; i++)
#pragma unroll
        for (int j = 0; j < 8; j++) acc[i][j] = 0.f;

    // prologue: tile 0 into stage 0 (k 0..15 all valid)
    {
        float4 a = *(const float4*)(Arow + lk);
        float4 b = *(const float4*)(Brow + lk);
        As[0][lk + 0][lrow] = a.x; As[0][lk + 1][lrow] = a.y;
        As[0][lk + 2][lrow] = a.z; As[0][lk + 3][lrow] = a.w;
        Bs[0][lk + 0][lrow] = b.x; Bs[0][lk + 1][lrow] = b.y;
        Bs[0][lk + 2][lrow] = b.z; Bs[0][lk + 3][lrow] = b.w;
    }

    for (int t = 0; t < NTILE; t++) {
        int st = t & 1;
        bool haveNext = (t + 1) < NTILE;
        float sa[4], sb[4];
        if (haveNext) {
            int k0 = (t + 1) * BK + lk;
            if (t + 1 < NTILE - 1) {
                float4 a = *(const float4*)(Arow + k0);
                float4 b = *(const float4*)(Brow + k0);
                sa[0] = a.x; sa[1] = a.y; sa[2] = a.z; sa[3] = a.w;
                sb[0] = b.x; sb[1] = b.y; sb[2] = b.z; sb[3] = b.w;
            } else {
#pragma unroll
                for (int i = 0; i < 4; i++) {
                    int k = k0 + i;
                    sa[i] = (k < IN_F) ? Arow[k] : 0.f;
                    sb[i] = (k < IN_F) ? Brow[k] : 0.f;
                }
            }
        }

        __syncthreads();

#pragma unroll
        for (int k = 0; k < BK; k++) {
            float4 av = *(const float4*)&As[st][k][ty * 4];
            float4 b0 = *(const float4*)&Bs[st][k][tx * 8];
            float4 b1 = *(const float4*)&Bs[st][k][tx * 8 + 4];
            float a[4] = {av.x, av.y, av.z, av.w};
            float b[8] = {b0.x, b0.y, b0.z, b0.w, b1.x, b1.y, b1.z, b1.w};
#pragma unroll
            for (int i = 0; i < 4; i++)
#pragma unroll
                for (int j = 0; j < 8; j++) acc[i][j] += a[i] * b[j];
        }

        if (haveNext) {
            int ns = st ^ 1;
#pragma unroll
            for (int i = 0; i < 4; i++) {
                As[ns][lk + i][lrow] = sa[i];
                Bs[ns][lk + i][lrow] = sb[i];
            }
        }
    }

#pragma unroll
    for (int i = 0; i < 4; i++) {
        float* Crow = g_inp + (bm + ty * 4 + i) * HID + bn + tx * 8;
        *(float4*)Crow       = make_float4(acc[i][0], acc[i][1], acc[i][2], acc[i][3]);
        *(float4*)(Crow + 4) = make_float4(acc[i][4], acc[i][5], acc[i][6], acc[i][7]);
    }

    __syncthreads();
    __threadfence();                      // release g_inp writes
    if (tid == 0) atomicAdd(&g_done[my], 1u);
}

// ---------------------------------------------------------------------------
// consumer: recurrent scan, 2 batches per CTA, 512 threads
// ---------------------------------------------------------------------------
__device__ void rsnn_part(SmemU* sm, const float* __restrict__ w_out,
                          float* __restrict__ out_hist,
                          float* __restrict__ spk_hist, int bid) {
    int tid = threadIdx.x;
    int lane = tid & 31;
    int warp = tid >> 5;               // 0..15

    if (tid < 4)  ((int*)sm->r.cnt)[tid] = 0;
    if (tid < 2 * OUT_F) ((float*)sm->r.out)[tid] = 0.f;

    float syn[2][2] = {{0.f, 0.f}, {0.f, 0.f}};
    float mem[2][2] = {{0.f, 0.f}, {0.f, 0.f}};

    int B0 = bid * 2;
    const unsigned lmask = (1u << lane) - 1u;

    __syncthreads();

    for (int t = 0; t < T_STEPS; t++) {
        int p = t & 1, q = p ^ 1;

        // wait for g_inp tiles of this step (produced by gemm CTAs)
        if (tid == 0) {
            while (ld_acq(&g_done[2 * t]) < (unsigned)NGX ||
                   ld_acq(&g_done[2 * t + 1]) < (unsigned)NGX)
                __nanosleep(64);
        }
        __syncthreads();

        // input drive
        float inpv[2][2];
#pragma unroll
        for (int g = 0; g < 2; g++) {
            const float* ib = g_inp + ((size_t)t * BATCH + (B0 + g)) * HID;
            inpv[g][0] = ib[tid];
            inpv[g][1] = ib[tid + 512];
        }

        // sparse recurrent gather (ascending j per batch, R1 order)
        float rr[2][2];
#pragma unroll
        for (int g = 0; g < 2; g++) {
            int s = sm->r.cnt[g][p];
            const int* lst = sm->r.list[g][p];
            float r0 = 0.f, r1 = 0.f;
            int i = 0;
            for (; i + 4 <= s; i += 4) {
                int j0 = lst[i], j1 = lst[i + 1], j2 = lst[i + 2], j3 = lst[i + 3];
                float a0 = g_wrecT[(size_t)j0 * HID + tid];
                float b0 = g_wrecT[(size_t)j0 * HID + tid + 512];
                float a1 = g_wrecT[(size_t)j1 * HID + tid];
                float b1 = g_wrecT[(size_t)j1 * HID + tid + 512];
                float a2 = g_wrecT[(size_t)j2 * HID + tid];
                float b2 = g_wrecT[(size_t)j2 * HID + tid + 512];
                float a3 = g_wrecT[(size_t)j3 * HID + tid];
                float b3 = g_wrecT[(size_t)j3 * HID + tid + 512];
                r0 += a0; r0 += a1; r0 += a2; r0 += a3;
                r1 += b0; r1 += b1; r1 += b2; r1 += b3;
            }
            for (; i < s; i++) {
                int j = lst[i];
                r0 += g_wrecT[(size_t)j * HID + tid];
                r1 += g_wrecT[(size_t)j * HID + tid + 512];
            }
            rr[g][0] = r0; rr[g][1] = r1;
        }

        // neuron update (R1 formulas, per (g,h))
        bool z[2][2];
#pragma unroll
        for (int g = 0; g < 2; g++) {
            float* sb = spk_hist + ((size_t)(B0 + g) * T_STEPS + t) * HID;
#pragma unroll
            for (int hh = 0; hh < 2; hh++) {
                float sv = (syn[g][hh] + inpv[g][hh] + rr[g][hh]) * ALPHA_S;
                syn[g][hh] = sv;
                bool zz = mem[g][hh] > 1.0f;
                mem[g][hh] = (zz ? sv : (mem[g][hh] + sv)) * ALPHA_N;
                z[g][hh] = zz;
                sb[tid + hh * 512] = zz ? 1.0f : 0.0f;
            }
        }

        // build next spike lists (ascending h: half A then half B)
#pragma unroll
        for (int g = 0; g < 2; g++) {
            unsigned bal0 = __ballot_sync(0xffffffffu, z[g][0]);
            unsigned bal1 = __ballot_sync(0xffffffffu, z[g][1]);
            if (lane == 0) {
                sm->r.c32[warp] = __popc(bal0);
                sm->r.c32[16 + warp] = __popc(bal1);
            }
            __syncthreads();
            if (warp == 0) {
                int v = sm->r.c32[lane];
#pragma unroll
                for (int off = 1; off < 32; off <<= 1) {
                    int n = __shfl_up_sync(0xffffffffu, v, off);
                    if (lane >= off) v += n;
                }
                sm->r.off[lane] = v;                  // inclusive
                if (lane == 31) sm->r.cnt[g][q] = v;
            }
            __syncthreads();
            if (z[g][0]) {
                int base = warp ? sm->r.off[warp - 1] : 0;
                sm->r.list[g][q][base + __popc(bal0 & lmask)] = tid;
            }
            if (z[g][1]) {
                int base = sm->r.off[15 + warp];      // warp==0 -> off[15]
                sm->r.list[g][q][base + __popc(bal1 & lmask)] = tid + 512;
            }
            __syncthreads();
        }

        // readout (R1 order: lane-strided sum + shfl tree)
#pragma unroll
        for (int g = 0; g < 2; g++) {
            int cs = sm->r.cnt[g][q];
            const int* lst = sm->r.list[g][q];
            float* ob = out_hist + ((size_t)(B0 + g) * T_STEPS + t) * OUT_F;
            for (int o = warp; o < OUT_F; o += 16) {
                const float* wrow = w_out + (size_t)o * HID;
                float sum = 0.f;
                for (int k = lane; k < cs; k += 32)
                    sum += wrow[lst[k]];
#pragma unroll
                for (int off = 16; off; off >>= 1)
                    sum += __shfl_down_sync(0xffffffffu, sum, off);
                if (lane == 0) {
                    float ov = (sm->r.out[g][o] + sum) * ALPHA_S;
                    sm->r.out[g][o] = ov;
                    ob[o] = ov;
                }
            }
        }
        __syncthreads();
    }
}

// ---------------------------------------------------------------------------
__global__ void __launch_bounds__(512, 2) fused_kernel(
    const float* __restrict__ X, const float* __restrict__ W,
    const float* __restrict__ w_out,
    float* __restrict__ out_hist, float* __restrict__ spk_hist)
{
    __shared__ SmemU sm;
    int bid = blockIdx.x;
    if (bid < NR)
        rsnn_part(&sm, w_out, out_hist, spk_hist, bid);
    else
        gemm_part(&sm, X, W, bid - NR);
}

// ---------------------------------------------------------------------------
extern "C" void kernel_launch(void* const* d_in, const int* in_sizes, int n_in,
                              void* d_out, int out_size) {
    const float* x     = (const float*)d_in[0];
    const float* w_in  = (const float*)d_in[1];
    const float* w_rec = (const float*)d_in[2];
    const float* w_out = (const float*)d_in[3];

    float* out_hist = (float*)d_out;
    float* spk_hist = out_hist + (size_t)BATCH * T_STEPS * OUT_F;

    transpose_wrec<<<dim3(HID / 32, HID / 32), dim3(32, 8)>>>(w_rec);
    zero_flags<<<1, 512>>>();
    fused_kernel<<<NR + NGX * NGY, 512>>>(x, w_in, w_out, out_hist, spk_hist);
}

// round 10
// speedup vs baseline: 1.6923x; 1.6923x over previous
#include <cuda_runtime.h>
#include <cstdint>

// ===========================================================================
// RSNN forward (serial pipeline, R8-proven numerics).
// Phase 1: inp = x @ w_in^T fp32 SIMT GEMM (R8 verbatim: FFMA floor).
// Phase 2: recurrent scan, one CTA per batch, 256 threads, thread owns 4
//   consecutive neurons -> gather is one LDG.128 per (thread, spike): 4x
//   fewer LDG issues than R8's scalar gather. All accumulation orders
//   preserved (ascending spike index per h; list ascending h) -> bitwise
//   identical output to R8/R1.
// ===========================================================================

#define T_STEPS 250
#define BATCH   256
#define IN_F    700
#define HID     1024
#define OUT_F   20
#define M_TOTAL (T_STEPS * BATCH)   // 64000

#define ALPHA_S 0.9048374180359595f
#define ALPHA_N 0.9753099120283326f

#define BM 128
#define BN 128
#define BK 16
#define NTILE 44

// ---- scratch (device globals) ----
__device__ float g_inp[(size_t)M_TOTAL * HID];   // 262 MB
__device__ float g_wrecT[(size_t)HID * HID];     // 4 MB

// ---------------------------------------------------------------------------
__global__ void transpose_wrec(const float* __restrict__ w) {
    __shared__ float tile[32][33];
    int x0 = blockIdx.x * 32, y0 = blockIdx.y * 32;
    int tx = threadIdx.x, ty = threadIdx.y;
#pragma unroll
    for (int i = 0; i < 32; i += 8)
        tile[ty + i][tx] = w[(size_t)(y0 + ty + i) * HID + (x0 + tx)];
    __syncthreads();
#pragma unroll
    for (int i = 0; i < 32; i += 8)
        g_wrecT[(size_t)(x0 + ty + i) * HID + (y0 + tx)] = tile[tx][ty + i];
}

// ---------------------------------------------------------------------------
// fp32 GEMM (R8 verbatim)
// ---------------------------------------------------------------------------
__global__ void __launch_bounds__(256) gemm_in(const float* __restrict__ X,
                                               const float* __restrict__ W) {
    __shared__ float As[2][BK][BM];
    __shared__ float Bs[2][BK][BN];

    int tid = threadIdx.x;
    int tx = tid & 15;
    int ty = tid >> 4;
    int lr = tid >> 1;
    int lk = (tid & 1) * 8;

    size_t bm = (size_t)blockIdx.y * BM;
    size_t bn = (size_t)blockIdx.x * BN;

    float acc[8][8];
#pragma unroll
    for (int i = 0; i < 8; i++)
#pragma unroll
        for (int j = 0; j < 8; j++) acc[i][j] = 0.f;

    const float* Arow = X + (bm + lr) * IN_F;
    const float* Brow = W + (bn + lr) * IN_F;

    {
        float4 a0 = *(const float4*)(Arow + lk);
        float4 a1 = *(const float4*)(Arow + lk + 4);
        float4 b0 = *(const float4*)(Brow + lk);
        float4 b1 = *(const float4*)(Brow + lk + 4);
        As[0][lk + 0][lr] = a0.x; As[0][lk + 1][lr] = a0.y;
        As[0][lk + 2][lr] = a0.z; As[0][lk + 3][lr] = a0.w;
        As[0][lk + 4][lr] = a1.x; As[0][lk + 5][lr] = a1.y;
        As[0][lk + 6][lr] = a1.z; As[0][lk + 7][lr] = a1.w;
        Bs[0][lk + 0][lr] = b0.x; Bs[0][lk + 1][lr] = b0.y;
        Bs[0][lk + 2][lr] = b0.z; Bs[0][lk + 3][lr] = b0.w;
        Bs[0][lk + 4][lr] = b1.x; Bs[0][lk + 5][lr] = b1.y;
        Bs[0][lk + 6][lr] = b1.z; Bs[0][lk + 7][lr] = b1.w;
    }

    for (int t = 0; t < NTILE; t++) {
        int st = t & 1;
        bool haveNext = (t + 1) < NTILE;
        float sa[8], sb[8];
        if (haveNext) {
            int k0 = (t + 1) * BK;
            if (t + 1 < NTILE - 1) {
                float4 a0 = *(const float4*)(Arow + k0 + lk);
                float4 a1 = *(const float4*)(Arow + k0 + lk + 4);
                float4 b0 = *(const float4*)(Brow + k0 + lk);
                float4 b1 = *(const float4*)(Brow + k0 + lk + 4);
                sa[0] = a0.x; sa[1] = a0.y; sa[2] = a0.z; sa[3] = a0.w;
                sa[4] = a1.x; sa[5] = a1.y; sa[6] = a1.z; sa[7] = a1.w;
                sb[0] = b0.x; sb[1] = b0.y; sb[2] = b0.z; sb[3] = b0.w;
                sb[4] = b1.x; sb[5] = b1.y; sb[6] = b1.z; sb[7] = b1.w;
            } else {
#pragma unroll
                for (int i = 0; i < 8; i++) {
                    int k = k0 + lk + i;
                    sa[i] = (k < IN_F) ? Arow[k] : 0.f;
                    sb[i] = (k < IN_F) ? Brow[k] : 0.f;
                }
            }
        }

        __syncthreads();

#pragma unroll
        for (int k = 0; k < BK; k++) {
            float4 a0 = *(const float4*)&As[st][k][ty * 8];
            float4 a1 = *(const float4*)&As[st][k][ty * 8 + 4];
            float4 b0 = *(const float4*)&Bs[st][k][tx * 8];
            float4 b1 = *(const float4*)&Bs[st][k][tx * 8 + 4];
            float a[8] = {a0.x, a0.y, a0.z, a0.w, a1.x, a1.y, a1.z, a1.w};
            float b[8] = {b0.x, b0.y, b0.z, b0.w, b1.x, b1.y, b1.z, b1.w};
#pragma unroll
            for (int i = 0; i < 8; i++)
#pragma unroll
                for (int j = 0; j < 8; j++) acc[i][j] += a[i] * b[j];
        }

        if (haveNext) {
            int ns = st ^ 1;
#pragma unroll
            for (int i = 0; i < 8; i++) {
                As[ns][lk + i][lr] = sa[i];
                Bs[ns][lk + i][lr] = sb[i];
            }
        }
    }

#pragma unroll
    for (int i = 0; i < 8; i++) {
        float* Crow = g_inp + (bm + ty * 8 + i) * HID + bn + tx * 8;
        *(float4*)Crow       = make_float4(acc[i][0], acc[i][1], acc[i][2], acc[i][3]);
        *(float4*)(Crow + 4) = make_float4(acc[i][4], acc[i][5], acc[i][6], acc[i][7]);
    }
}

// ---------------------------------------------------------------------------
// recurrent scan: 1 CTA per batch, 256 threads, 4 neurons/thread (float4).
// ---------------------------------------------------------------------------
__global__ void __launch_bounds__(256, 4) rsnn_kernel(
    const float* __restrict__ w_out,
    float* __restrict__ out_hist,
    float* __restrict__ spk_hist)
{
    int b = blockIdx.x;
    int tid = threadIdx.x;          // owns h = 4*tid .. 4*tid+3
    int lane = tid & 31;
    int warp = tid >> 5;            // 0..7

    __shared__ int   s_list[2][HID];
    __shared__ int   s_cnt[2];
    __shared__ int   s_wsum[8];
    __shared__ float s_out[OUT_F];

    if (tid < 2) s_cnt[tid] = 0;
    if (tid < OUT_F) s_out[tid] = 0.f;

    float syn0 = 0.f, syn1 = 0.f, syn2 = 0.f, syn3 = 0.f;
    float mem0 = 0.f, mem1 = 0.f, mem2 = 0.f, mem3 = 0.f;

    const float* inp_b = g_inp + (size_t)b * HID + 4 * tid;
    float* spk_b = spk_hist + (size_t)b * T_STEPS * HID + 4 * tid;
    float* out_b = out_hist + (size_t)b * T_STEPS * OUT_F;
    const float* wrec_c = g_wrecT + 4 * tid;

    __syncthreads();

    for (int t = 0; t < T_STEPS; t++) {
        int p = t & 1, q = p ^ 1;

        float4 inpv = *(const float4*)(inp_b + (size_t)t * (BATCH * HID));

        // sparse recurrent gather: one LDG.128 per spike, ascending index
        int s = s_cnt[p];
        const int* lst = s_list[p];
        float r0 = 0.f, r1 = 0.f, r2 = 0.f, r3 = 0.f;
        int i = 0;
        for (; i + 4 <= s; i += 4) {
            int j0 = lst[i], j1 = lst[i + 1], j2 = lst[i + 2], j3 = lst[i + 3];
            float4 v0 = *(const float4*)(wrec_c + (size_t)j0 * HID);
            float4 v1 = *(const float4*)(wrec_c + (size_t)j1 * HID);
            float4 v2 = *(const float4*)(wrec_c + (size_t)j2 * HID);
            float4 v3 = *(const float4*)(wrec_c + (size_t)j3 * HID);
            r0 += v0.x; r1 += v0.y; r2 += v0.z; r3 += v0.w;
            r0 += v1.x; r1 += v1.y; r2 += v1.z; r3 += v1.w;
            r0 += v2.x; r1 += v2.y; r2 += v2.z; r3 += v2.w;
            r0 += v3.x; r1 += v3.y; r2 += v3.z; r3 += v3.w;
        }
        for (; i < s; i++) {
            float4 v = *(const float4*)(wrec_c + (size_t)lst[i] * HID);
            r0 += v.x; r1 += v.y; r2 += v.z; r3 += v.w;
        }

        // neuron updates (R1 formulas, per h)
        float sv0 = (syn0 + inpv.x + r0) * ALPHA_S;
        float sv1 = (syn1 + inpv.y + r1) * ALPHA_S;
        float sv2 = (syn2 + inpv.z + r2) * ALPHA_S;
        float sv3 = (syn3 + inpv.w + r3) * ALPHA_S;
        syn0 = sv0; syn1 = sv1; syn2 = sv2; syn3 = sv3;
        bool z0 = mem0 > 1.0f, z1 = mem1 > 1.0f, z2 = mem2 > 1.0f, z3 = mem3 > 1.0f;
        mem0 = (z0 ? sv0 : (mem0 + sv0)) * ALPHA_N;
        mem1 = (z1 ? sv1 : (mem1 + sv1)) * ALPHA_N;
        mem2 = (z2 ? sv2 : (mem2 + sv2)) * ALPHA_N;
        mem3 = (z3 ? sv3 : (mem3 + sv3)) * ALPHA_N;

        *(float4*)(spk_b + (size_t)t * HID) = make_float4(
            z0 ? 1.f : 0.f, z1 ? 1.f : 0.f, z2 ? 1.f : 0.f, z3 ? 1.f : 0.f);

        // deterministic compaction, list ascending h
        int nz = (int)z0 + (int)z1 + (int)z2 + (int)z3;
        int v = nz;
#pragma unroll
        for (int off = 1; off < 32; off <<= 1) {
            int n = __shfl_up_sync(0xffffffffu, v, off);
            if (lane >= off) v += n;
        }
        if (lane == 31) s_wsum[warp] = v;      // warp total
        __syncthreads();
        if (tid == 0) {
            int run = 0;
#pragma unroll
            for (int w = 0; w < 8; w++) { run += s_wsum[w]; s_wsum[w] = run; }
            s_cnt[q] = run;
        }
        __syncthreads();
        {
            int base = (warp ? s_wsum[warp - 1] : 0) + (v - nz);
            int h0 = 4 * tid;
            int* dst = s_list[q];
            if (z0) dst[base++] = h0;
            if (z1) dst[base++] = h0 + 1;
            if (z2) dst[base++] = h0 + 2;
            if (z3) dst[base++] = h0 + 3;
        }
        __syncthreads();

        // readout (same per-o add order as R1)
        int cs = s_cnt[q];
        const int* lq = s_list[q];
        for (int o = warp; o < OUT_F; o += 8) {
            const float* wrow = w_out + (size_t)o * HID;
            float sum = 0.f;
            for (int k = lane; k < cs; k += 32)
                sum += wrow[lq[k]];
#pragma unroll
            for (int off = 16; off; off >>= 1)
                sum += __shfl_down_sync(0xffffffffu, sum, off);
            if (lane == 0) {
                float ov = (s_out[o] + sum) * ALPHA_S;
                s_out[o] = ov;
                out_b[(size_t)t * OUT_F + o] = ov;
            }
        }
        __syncthreads();
    }
}

// ---------------------------------------------------------------------------
extern "C" void kernel_launch(void* const* d_in, const int* in_sizes, int n_in,
                              void* d_out, int out_size) {
    const float* x     = (const float*)d_in[0];
    const float* w_in  = (const float*)d_in[1];
    const float* w_rec = (const float*)d_in[2];
    const float* w_out = (const float*)d_in[3];

    float* out_hist = (float*)d_out;
    float* spk_hist = out_hist + (size_t)BATCH * T_STEPS * OUT_F;

    transpose_wrec<<<dim3(HID / 32, HID / 32), dim3(32, 8)>>>(w_rec);
    gemm_in<<<dim3(HID / BN, M_TOTAL / BM), 256>>>(x, w_in);
    rsnn_kernel<<<BATCH, 256>>>(w_out, out_hist, spk_hist);
}